// round 7
// baseline (speedup 1.0000x reference)
#include <cuda_runtime.h>
#include <cuda_fp16.h>
#include <cstdint>

// Problem constants
#define NN     8192
#define INDIM  256
#define DTOT   128      // OUT_DIM * HEADS
#define NCP    144      // padded GEMM N: 128 outputs + 2 denominators + 14 zero pad
#define MT     128      // M tile
#define KT     64       // K tile
#define KSPLIT 4096     // K per split (split-K = 2)
#define NKI    64       // K iterations per split

// -------- static device scratch (no allocations allowed) --------
__device__ float     g_h[NN * DTOT];            // 4 MB   h = x @ W^T (fp32)
__device__ float     g_er[2 * NN];              // er per head
__device__ unsigned  g_maxkey[2];               // encoded global max of er per head
__device__ __half    g_g[NCP * NN];             // 2.25 MB  G^T fp16 [NCP][NN]
__device__ float     g_part[2u * NN * NCP];     // 9.4 MB split-K partials

__device__ __forceinline__ uint32_t smem_u32(const void* p) {
    uint32_t a;
    asm("{ .reg .u64 t; cvta.to.shared.u64 t, %1; cvt.u32.u64 %0, t; }" : "=r"(a) : "l"(p));
    return a;
}
#define SWZ(off) ((off) ^ (((off) >> 3) & 0x70))

// ordered-uint encoding for float atomicMax
__device__ __forceinline__ unsigned enc_f(float f) {
    unsigned b = __float_as_uint(f);
    return (b & 0x80000000u) ? ~b : (b | 0x80000000u);
}
__device__ __forceinline__ float dec_f(unsigned k) {
    return (k & 0x80000000u) ? __uint_as_float(k & 0x7FFFFFFFu) : __uint_as_float(~k);
}

// ======================= k1: h = x @ W^T (fp32, register tiled) =======================
// grid 128 = 64 m-tiles x 2 n-tiles, block 256. Tile 128x64, K-chunks of 32.
__global__ void __launch_bounds__(256) k1_h_gemm(const float* __restrict__ x,
                                                const float* __restrict__ W) {
    if (blockIdx.x == 0 && threadIdx.x < 2) g_maxkey[threadIdx.x] = 0u;  // reset for k2a

    __shared__ __align__(16) float xs[32][132];  // k-major [kk][i]
    __shared__ __align__(16) float ws[32][68];   // k-major [kk][c]
    int tid = threadIdx.x;
    int mtile = blockIdx.x >> 1, ntile = blockIdx.x & 1;
    int i0 = mtile * 128, n0 = ntile * 64;
    int tx = tid & 15, ty = tid >> 4;
    int r0 = ty * 8, c0 = tx * 4;

    float acc[8][4];
#pragma unroll
    for (int m = 0; m < 8; ++m)
#pragma unroll
        for (int n = 0; n < 4; ++n) acc[m][n] = 0.f;

    for (int kc = 0; kc < 8; ++kc) {
        int k0 = kc * 32;
#pragma unroll
        for (int i = 0; i < 4; ++i) {          // x tile: 1024 float4
            int q = tid + i * 256;
            int r = q >> 3, c4 = q & 7;
            float4 v = *(const float4*)(x + (size_t)(i0 + r) * INDIM + k0 + c4 * 4);
            xs[c4 * 4 + 0][r] = v.x; xs[c4 * 4 + 1][r] = v.y;
            xs[c4 * 4 + 2][r] = v.z; xs[c4 * 4 + 3][r] = v.w;
        }
#pragma unroll
        for (int i = 0; i < 2; ++i) {          // W tile: 512 float4
            int q = tid + i * 256;
            int r = q >> 3, c4 = q & 7;
            float4 v = *(const float4*)(W + (size_t)(n0 + r) * INDIM + k0 + c4 * 4);
            ws[c4 * 4 + 0][r] = v.x; ws[c4 * 4 + 1][r] = v.y;
            ws[c4 * 4 + 2][r] = v.z; ws[c4 * 4 + 3][r] = v.w;
        }
        __syncthreads();
#pragma unroll
        for (int kk = 0; kk < 32; ++kk) {
            float4 a0 = *(const float4*)&xs[kk][r0];
            float4 a1 = *(const float4*)&xs[kk][r0 + 4];
            float4 bv = *(const float4*)&ws[kk][c0];
            float a[8] = {a0.x, a0.y, a0.z, a0.w, a1.x, a1.y, a1.z, a1.w};
            float b[4] = {bv.x, bv.y, bv.z, bv.w};
#pragma unroll
            for (int m = 0; m < 8; ++m)
#pragma unroll
                for (int n = 0; n < 4; ++n) acc[m][n] += a[m] * b[n];
        }
        __syncthreads();
    }
#pragma unroll
    for (int m = 0; m < 8; ++m) {
        float4 v = make_float4(acc[m][0], acc[m][1], acc[m][2], acc[m][3]);
        *(float4*)(g_h + (size_t)(i0 + r0 + m) * DTOT + n0 + c0) = v;
    }
}

// ======================= k2a: er[j,h] + global max per head =======================
__global__ void __launch_bounds__(256) k2a_er(const float* __restrict__ attn_r) {
    int tid = threadIdx.x, lane = tid & 31, wid = tid >> 5;
    int j = blockIdx.x * 256 + tid;
    const float* hp = g_h + (size_t)j * DTOT;
    float er0 = 0.f, er1 = 0.f;
#pragma unroll
    for (int d = 0; d < 64; ++d) {
        er0 += hp[d]      * attn_r[d];
        er1 += hp[64 + d] * attn_r[64 + d];
    }
    g_er[j] = er0;
    g_er[NN + j] = er1;

    float m0 = er0, m1 = er1;
#pragma unroll
    for (int o = 16; o; o >>= 1) {
        m0 = fmaxf(m0, __shfl_xor_sync(0xFFFFFFFFu, m0, o));
        m1 = fmaxf(m1, __shfl_xor_sync(0xFFFFFFFFu, m1, o));
    }
    __shared__ float s0[8], s1[8];
    if (lane == 0) { s0[wid] = m0; s1[wid] = m1; }
    __syncthreads();
    if (tid == 0) {
#pragma unroll
        for (int w = 1; w < 8; ++w) { m0 = fmaxf(m0, s0[w]); m1 = fmaxf(m1, s1[w]); }
        m0 = fmaxf(m0, s0[0]); m1 = fmaxf(m1, s1[0]);
        atomicMax(&g_maxkey[0], enc_f(m0));
        atomicMax(&g_maxkey[1], enc_f(m1));
    }
}

// ======================= k2b: G^T = exp(er - max) * h  (fp16) =======================
__global__ void __launch_bounds__(256) k2b_build_g() {
    int j = blockIdx.x * 256 + threadIdx.x;
    float m0 = dec_f(g_maxkey[0]), m1 = dec_f(g_maxkey[1]);
    float E0 = expf(g_er[j] - m0);
    float E1 = expf(g_er[NN + j] - m1);
    const float* hp = g_h + (size_t)j * DTOT;
    float hr[128];
#pragma unroll
    for (int i = 0; i < 32; ++i) {
        float4 v = *(const float4*)(hp + i * 4);
        hr[i * 4 + 0] = v.x; hr[i * 4 + 1] = v.y; hr[i * 4 + 2] = v.z; hr[i * 4 + 3] = v.w;
    }
#pragma unroll
    for (int c = 0; c < 128; ++c) {
        float v = (c < 64 ? E0 : E1) * hr[c];
        g_g[(size_t)c * NN + j] = __float2half(v);
    }
    g_g[(size_t)128 * NN + j] = __float2half(E0);
    g_g[(size_t)129 * NN + j] = __float2half(E1);
#pragma unroll
    for (int c = 130; c < NCP; ++c) g_g[(size_t)c * NN + j] = __float2half(0.f);
}

// ======================= k3: [num|den] = f16(adj) @ G  (mma.sync, split-K 2) =======================
// dyn smem: buf b at b*BUFB: A 128x64 f16 (16 KB, SW128) then B 144x64 f16 (18 KB, SW128)
#define BUFB  34816
#define SMEM3 (2 * BUFB)

__device__ __forceinline__ void cpa_B(uint32_t Bb, int j0, int tid) {
#pragma unroll
    for (int i = 0; i < 5; ++i) {
        int q = tid + i * 256;
        if (q < NCP * 8) {
            int n = q >> 3, c = q & 7;
            uint32_t dst = Bb + SWZ((uint32_t)(n * 128 + c * 16));
            const void* gp = (const char*)g_g + ((size_t)n * NN + j0) * 2 + c * 16;
            asm volatile("cp.async.cg.shared.global [%0], [%1], 16;" :: "r"(dst), "l"(gp));
        }
    }
}
__device__ __forceinline__ void lda(int4* v, const int* __restrict__ adj,
                                    int i0, int j0, int tid) {
#pragma unroll
    for (int i = 0; i < 8; ++i) {
        int q = tid + i * 256;
        int r = q >> 4, c4 = q & 15;
        v[i] = *(const int4*)(adj + (size_t)(i0 + r) * NN + j0 + c4 * 4);
    }
}
__device__ __forceinline__ void sts_A(uint32_t Ab, const int4* v, int tid) {
#pragma unroll
    for (int i = 0; i < 8; ++i) {
        int q = tid + i * 256;
        int r = q >> 4, c4 = q & 15;
        uint32_t p0 = ((uint32_t)v[i].x | ((uint32_t)v[i].y << 16)) * 0x3C00u;
        uint32_t p1 = ((uint32_t)v[i].z | ((uint32_t)v[i].w << 16)) * 0x3C00u;
        uint32_t off = Ab + SWZ((uint32_t)(r * 128 + c4 * 8));
        asm volatile("st.shared.v2.b32 [%0], {%1, %2};" :: "r"(off), "r"(p0), "r"(p1));
    }
}

__device__ __forceinline__ void compute_iter(uint32_t Ab, uint32_t Bb,
                                             float acc[2][9][4],
                                             const uint32_t arow[2],
                                             const uint32_t brow4[4],
                                             uint32_t brow2) {
#pragma unroll
    for (int s = 0; s < 4; ++s) {
        uint32_t kb = s * 32;
        uint32_t a[2][4];
#pragma unroll
        for (int mf = 0; mf < 2; ++mf) {
            uint32_t ad = Ab + SWZ(arow[mf] + kb);
            asm volatile("ldmatrix.sync.aligned.m8n8.x4.shared.b16 {%0,%1,%2,%3}, [%4];"
                : "=r"(a[mf][0]), "=r"(a[mf][1]), "=r"(a[mf][2]), "=r"(a[mf][3]) : "r"(ad));
        }
        uint32_t b[9][2];
#pragma unroll
        for (int g4 = 0; g4 < 4; ++g4) {
            uint32_t bd = Bb + SWZ(brow4[g4] + kb);
            asm volatile("ldmatrix.sync.aligned.m8n8.x4.shared.b16 {%0,%1,%2,%3}, [%4];"
                : "=r"(b[2 * g4][0]), "=r"(b[2 * g4][1]),
                  "=r"(b[2 * g4 + 1][0]), "=r"(b[2 * g4 + 1][1]) : "r"(bd));
        }
        {
            uint32_t bd = Bb + SWZ(brow2 + kb);
            asm volatile("ldmatrix.sync.aligned.m8n8.x2.shared.b16 {%0,%1}, [%2];"
                : "=r"(b[8][0]), "=r"(b[8][1]) : "r"(bd));
        }
#pragma unroll
        for (int mf = 0; mf < 2; ++mf)
#pragma unroll
            for (int nf = 0; nf < 9; ++nf)
                asm volatile(
                    "mma.sync.aligned.m16n8k16.row.col.f32.f16.f16.f32 "
                    "{%0,%1,%2,%3}, {%4,%5,%6,%7}, {%8,%9}, {%0,%1,%2,%3};"
                    : "+f"(acc[mf][nf][0]), "+f"(acc[mf][nf][1]),
                      "+f"(acc[mf][nf][2]), "+f"(acc[mf][nf][3])
                    : "r"(a[mf][0]), "r"(a[mf][1]), "r"(a[mf][2]), "r"(a[mf][3]),
                      "r"(b[nf][0]), "r"(b[nf][1]));
    }
}

__global__ void __launch_bounds__(256, 1) k3_adj_gemm(const int* __restrict__ adj) {
    extern __shared__ char sm3[];
    uint32_t sb = smem_u32(sm3);
    int tid = threadIdx.x, lane = tid & 31, wid = tid >> 5;
    int wm = wid & 3, wn = wid >> 2;          // 4 (M) x 2 (N) warps
    int lt = lane >> 3, lr = lane & 7;
    int mtile = blockIdx.x >> 1, sp = blockIdx.x & 1;
    int i0 = mtile * MT, jb = sp * KSPLIT;

    // per-lane ldmatrix base offsets (pre-swizzle)
    uint32_t arow[2], brow4[4], brow2;
#pragma unroll
    for (int mf = 0; mf < 2; ++mf)
        arow[mf] = (uint32_t)((wm * 32 + mf * 16 + (lt & 1) * 8 + lr) * 128 + (lt >> 1) * 16);
#pragma unroll
    for (int g4 = 0; g4 < 4; ++g4)
        brow4[g4] = (uint32_t)((wn * 72 + g4 * 16 + (lt >> 1) * 8 + lr) * 128 + (lt & 1) * 16);
    brow2 = (uint32_t)((wn * 72 + 64 + lr) * 128 + (lt & 1) * 16);

    float acc[2][9][4];
#pragma unroll
    for (int mf = 0; mf < 2; ++mf)
#pragma unroll
        for (int nf = 0; nf < 9; ++nf)
#pragma unroll
            for (int q = 0; q < 4; ++q) acc[mf][nf][q] = 0.f;

    uint32_t Ab[2] = {sb, sb + BUFB};
    uint32_t Bb[2] = {sb + 16384, sb + BUFB + 16384};
    int4 v[8];

    // prologue: stage tile 0
    cpa_B(Bb[0], jb, tid);
    asm volatile("cp.async.commit_group;" ::: "memory");
    lda(v, adj, i0, jb, tid);
    sts_A(Ab[0], v, tid);
    asm volatile("cp.async.wait_group 0;" ::: "memory");
    __syncthreads();

    for (int it = 0; it < NKI; ++it) {
        int b = it & 1;
        if (it + 1 < NKI) {
            cpa_B(Bb[b ^ 1], jb + (it + 1) * KT, tid);
            asm volatile("cp.async.commit_group;" ::: "memory");
            lda(v, adj, i0, jb + (it + 1) * KT, tid);
        }
        compute_iter(Ab[b], Bb[b], acc, arow, brow4, brow2);
        if (it + 1 < NKI) sts_A(Ab[b ^ 1], v, tid);
        asm volatile("cp.async.wait_group 0;" ::: "memory");
        __syncthreads();
    }

    // epilogue: store split-K partials
    int r0 = i0 + wm * 32 + (lane >> 2);
    int c0 = wn * 72 + (lane & 3) * 2;
    float* base = g_part + (size_t)sp * NN * NCP;
#pragma unroll
    for (int mf = 0; mf < 2; ++mf)
#pragma unroll
        for (int nf = 0; nf < 9; ++nf) {
            int row = r0 + mf * 16, col = c0 + nf * 8;
            *(float2*)(base + (size_t)row * NCP + col) =
                make_float2(acc[mf][nf][0], acc[mf][nf][1]);
            *(float2*)(base + (size_t)(row + 8) * NCP + col) =
                make_float2(acc[mf][nf][2], acc[mf][nf][3]);
        }
}

// ======================= k4: combine splits + divide =======================
__global__ void __launch_bounds__(256) k4_finalize(float* __restrict__ out) {
    int g = blockIdx.x * 256 + threadIdx.x;   // over 8192*128
    int i = g >> 7, c = g & 127;
    const float* p0 = g_part + (size_t)i * NCP;
    const float* p1 = g_part + ((size_t)NN + i) * NCP;
    float num = p0[c] + p1[c];
    int hh = c >> 6;
    float den = p0[128 + hh] + p1[128 + hh];
    out[g] = num / den;
}

// ======================= launch =======================
extern "C" void kernel_launch(void* const* d_in, const int* in_sizes, int n_in,
                              void* d_out, int out_size) {
    (void)in_sizes; (void)n_in; (void)out_size;
    const float* x      = (const float*)d_in[0];
    const int*   adj    = (const int*)d_in[1];
    const float* W      = (const float*)d_in[2];
    // d_in[3] = attn_l : cancels in the softmax over j — unused
    const float* attn_r = (const float*)d_in[4];
    float* out = (float*)d_out;

    cudaFuncSetAttribute(k3_adj_gemm, cudaFuncAttributeMaxDynamicSharedMemorySize, SMEM3);

    k1_h_gemm<<<128, 256>>>(x, W);
    k2a_er<<<32, 256>>>(attn_r);
    k2b_build_g<<<32, 256>>>();
    k3_adj_gemm<<<128, 256, SMEM3>>>(adj);
    k4_finalize<<<4096, 256>>>(out);
}

// round 8
// speedup vs baseline: 1.1669x; 1.1669x over previous
#include <cuda_runtime.h>
#include <cuda_fp16.h>
#include <cstdint>

// Problem constants
#define NN     8192
#define INDIM  256
#define DTOT   128      // OUT_DIM * HEADS
#define NCP    144      // padded GEMM N: 128 outputs + 2 denominators + 14 zero pad
#define MT     128      // M tile
#define KT     64       // K tile
#define KSPLIT 4096     // K per split (split-K = 2)
#define NKI    64       // K iterations per split

// -------- static device scratch (no allocations allowed) --------
__device__ float     g_h[NN * DTOT];            // 4 MB   h = x @ W^T (fp32)
__device__ float     g_er[2 * NN];              // er per head
__device__ unsigned  g_maxkey[2];               // encoded global max of er per head
__device__ __half    g_g[NCP * NN];             // 2.25 MB  G^T fp16 [NCP][NN]
__device__ float     g_part[2u * NN * NCP];     // 9.4 MB split-K partials

__device__ __forceinline__ uint32_t smem_u32(const void* p) {
    uint32_t a;
    asm("{ .reg .u64 t; cvta.to.shared.u64 t, %1; cvt.u32.u64 %0, t; }" : "=r"(a) : "l"(p));
    return a;
}
#define SWZ(off) ((off) ^ (((off) >> 3) & 0x70))

// ordered-uint encoding for float atomicMax
__device__ __forceinline__ unsigned enc_f(float f) {
    unsigned b = __float_as_uint(f);
    return (b & 0x80000000u) ? ~b : (b | 0x80000000u);
}
__device__ __forceinline__ float dec_f(unsigned k) {
    return (k & 0x80000000u) ? __uint_as_float(k & 0x7FFFFFFFu) : __uint_as_float(~k);
}

// ======================= k1: h = x @ W^T (fp32, register tiled) =======================
__global__ void __launch_bounds__(256) k1_h_gemm(const float* __restrict__ x,
                                                const float* __restrict__ W) {
    if (blockIdx.x == 0 && threadIdx.x < 2) g_maxkey[threadIdx.x] = 0u;  // reset for k2a

    __shared__ __align__(16) float xs[32][132];  // k-major [kk][i]
    __shared__ __align__(16) float ws[32][68];   // k-major [kk][c]
    int tid = threadIdx.x;
    int mtile = blockIdx.x >> 1, ntile = blockIdx.x & 1;
    int i0 = mtile * 128, n0 = ntile * 64;
    int tx = tid & 15, ty = tid >> 4;
    int r0 = ty * 8, c0 = tx * 4;

    float acc[8][4];
#pragma unroll
    for (int m = 0; m < 8; ++m)
#pragma unroll
        for (int n = 0; n < 4; ++n) acc[m][n] = 0.f;

    for (int kc = 0; kc < 8; ++kc) {
        int k0 = kc * 32;
#pragma unroll
        for (int i = 0; i < 4; ++i) {          // x tile: 1024 float4
            int q = tid + i * 256;
            int r = q >> 3, c4 = q & 7;
            float4 v = *(const float4*)(x + (size_t)(i0 + r) * INDIM + k0 + c4 * 4);
            xs[c4 * 4 + 0][r] = v.x; xs[c4 * 4 + 1][r] = v.y;
            xs[c4 * 4 + 2][r] = v.z; xs[c4 * 4 + 3][r] = v.w;
        }
#pragma unroll
        for (int i = 0; i < 2; ++i) {          // W tile: 512 float4
            int q = tid + i * 256;
            int r = q >> 3, c4 = q & 7;
            float4 v = *(const float4*)(W + (size_t)(n0 + r) * INDIM + k0 + c4 * 4);
            ws[c4 * 4 + 0][r] = v.x; ws[c4 * 4 + 1][r] = v.y;
            ws[c4 * 4 + 2][r] = v.z; ws[c4 * 4 + 3][r] = v.w;
        }
        __syncthreads();
#pragma unroll
        for (int kk = 0; kk < 32; ++kk) {
            float4 a0 = *(const float4*)&xs[kk][r0];
            float4 a1 = *(const float4*)&xs[kk][r0 + 4];
            float4 bv = *(const float4*)&ws[kk][c0];
            float a[8] = {a0.x, a0.y, a0.z, a0.w, a1.x, a1.y, a1.z, a1.w};
            float b[4] = {bv.x, bv.y, bv.z, bv.w};
#pragma unroll
            for (int m = 0; m < 8; ++m)
#pragma unroll
                for (int n = 0; n < 4; ++n) acc[m][n] += a[m] * b[n];
        }
        __syncthreads();
    }
#pragma unroll
    for (int m = 0; m < 8; ++m) {
        float4 v = make_float4(acc[m][0], acc[m][1], acc[m][2], acc[m][3]);
        *(float4*)(g_h + (size_t)(i0 + r0 + m) * DTOT + n0 + c0) = v;
    }
}

// ======================= k2a: er[j,h] + global max per head =======================
__global__ void __launch_bounds__(256) k2a_er(const float* __restrict__ attn_r) {
    int tid = threadIdx.x, lane = tid & 31, wid = tid >> 5;
    int j = blockIdx.x * 256 + tid;
    const float* hp = g_h + (size_t)j * DTOT;
    float er0 = 0.f, er1 = 0.f;
#pragma unroll
    for (int d = 0; d < 64; ++d) {
        er0 += hp[d]      * attn_r[d];
        er1 += hp[64 + d] * attn_r[64 + d];
    }
    g_er[j] = er0;
    g_er[NN + j] = er1;

    float m0 = er0, m1 = er1;
#pragma unroll
    for (int o = 16; o; o >>= 1) {
        m0 = fmaxf(m0, __shfl_xor_sync(0xFFFFFFFFu, m0, o));
        m1 = fmaxf(m1, __shfl_xor_sync(0xFFFFFFFFu, m1, o));
    }
    __shared__ float s0[8], s1[8];
    if (lane == 0) { s0[wid] = m0; s1[wid] = m1; }
    __syncthreads();
    if (tid == 0) {
#pragma unroll
        for (int w = 1; w < 8; ++w) { m0 = fmaxf(m0, s0[w]); m1 = fmaxf(m1, s1[w]); }
        m0 = fmaxf(m0, s0[0]); m1 = fmaxf(m1, s1[0]);
        atomicMax(&g_maxkey[0], enc_f(m0));
        atomicMax(&g_maxkey[1], enc_f(m1));
    }
}

// ======================= k2b: G^T = exp(er - max) * h  (fp16) =======================
__global__ void __launch_bounds__(256) k2b_build_g() {
    int j = blockIdx.x * 256 + threadIdx.x;
    float m0 = dec_f(g_maxkey[0]), m1 = dec_f(g_maxkey[1]);
    float E0 = expf(g_er[j] - m0);
    float E1 = expf(g_er[NN + j] - m1);
    const float* hp = g_h + (size_t)j * DTOT;
    float hr[128];
#pragma unroll
    for (int i = 0; i < 32; ++i) {
        float4 v = *(const float4*)(hp + i * 4);
        hr[i * 4 + 0] = v.x; hr[i * 4 + 1] = v.y; hr[i * 4 + 2] = v.z; hr[i * 4 + 3] = v.w;
    }
#pragma unroll
    for (int c = 0; c < 128; ++c) {
        float v = (c < 64 ? E0 : E1) * hr[c];
        g_g[(size_t)c * NN + j] = __float2half(v);
    }
    g_g[(size_t)128 * NN + j] = __float2half(E0);
    g_g[(size_t)129 * NN + j] = __float2half(E1);
#pragma unroll
    for (int c = 130; c < NCP; ++c) g_g[(size_t)c * NN + j] = __float2half(0.f);
}

// ======================= k3: [num|den] = f16(adj) @ G  (mma.sync, 4-stage cp.async) =======================
// per stage: A as raw int32, 128 rows x 272B pitch (34816 B) ; B fp16 SW128 144x128B (18432 B)
#define APITCH 272
#define ABYTES 34816
#define STAGEB 53248
#define NSTG   4
#define SMEM3  (NSTG * STAGEB)

__device__ __forceinline__ void stage_load(uint32_t Sb, const int* __restrict__ adj,
                                           int i0, int j0, int tid) {
    uint32_t Ab = Sb, Bb = Sb + ABYTES;
    // A: 128 rows x 16 chunks of 16B (raw int32, no conversion)
#pragma unroll
    for (int i = 0; i < 8; ++i) {
        int q = tid + i * 256;
        int r = q >> 4, ch = q & 15;
        uint32_t dst = Ab + (uint32_t)(r * APITCH + ch * 16);
        const void* src = adj + (size_t)(i0 + r) * NN + j0 + ch * 4;
        asm volatile("cp.async.cg.shared.global [%0], [%1], 16;" :: "r"(dst), "l"(src));
    }
    // B: 144 rows x 8 chunks of 16B, SW128
#pragma unroll
    for (int i = 0; i < 5; ++i) {
        int q = tid + i * 256;
        if (q < NCP * 8) {
            int n = q >> 3, c = q & 7;
            uint32_t dst = Bb + SWZ((uint32_t)(n * 128 + c * 16));
            const void* src = (const char*)g_g + ((size_t)n * NN + j0) * 2 + c * 16;
            asm volatile("cp.async.cg.shared.global [%0], [%1], 16;" :: "r"(dst), "l"(src));
        }
    }
    asm volatile("cp.async.commit_group;" ::: "memory");
}

__device__ __forceinline__ void compute_iter(uint32_t Ab, uint32_t Bb,
                                             float acc[2][9][4],
                                             uint32_t aoff,
                                             const uint32_t brow4[4],
                                             uint32_t brow2) {
#pragma unroll
    for (int s = 0; s < 4; ++s) {
        uint32_t kb = s * 32;   // B byte offset within row (16 halfs per k-step)
        uint32_t ka = s * 64;   // A byte offset within row (16 ints per k-step)
        uint32_t a[2][4];
#pragma unroll
        for (int mf = 0; mf < 2; ++mf) {
            uint32_t base = Ab + aoff + (uint32_t)(mf * 16 * APITCH) + ka;
            uint32_t x0, y0, x1, y1, x2, y2, x3, y3;
            asm("ld.shared.v2.u32 {%0,%1}, [%2];" : "=r"(x0), "=r"(y0) : "r"(base));
            asm("ld.shared.v2.u32 {%0,%1}, [%2];" : "=r"(x1), "=r"(y1) : "r"(base + 8 * APITCH));
            asm("ld.shared.v2.u32 {%0,%1}, [%2];" : "=r"(x2), "=r"(y2) : "r"(base + 32));
            asm("ld.shared.v2.u32 {%0,%1}, [%2];" : "=r"(x3), "=r"(y3) : "r"(base + 8 * APITCH + 32));
            a[mf][0] = (x0 | (y0 << 16)) * 0x3C00u;
            a[mf][1] = (x1 | (y1 << 16)) * 0x3C00u;
            a[mf][2] = (x2 | (y2 << 16)) * 0x3C00u;
            a[mf][3] = (x3 | (y3 << 16)) * 0x3C00u;
        }
        uint32_t b[9][2];
#pragma unroll
        for (int g4 = 0; g4 < 4; ++g4) {
            uint32_t bd = Bb + SWZ(brow4[g4] + kb);
            asm volatile("ldmatrix.sync.aligned.m8n8.x4.shared.b16 {%0,%1,%2,%3}, [%4];"
                : "=r"(b[2 * g4][0]), "=r"(b[2 * g4][1]),
                  "=r"(b[2 * g4 + 1][0]), "=r"(b[2 * g4 + 1][1]) : "r"(bd));
        }
        {
            uint32_t bd = Bb + SWZ(brow2 + kb);
            asm volatile("ldmatrix.sync.aligned.m8n8.x2.shared.b16 {%0,%1}, [%2];"
                : "=r"(b[8][0]), "=r"(b[8][1]) : "r"(bd));
        }
#pragma unroll
        for (int mf = 0; mf < 2; ++mf)
#pragma unroll
            for (int nf = 0; nf < 9; ++nf)
                asm volatile(
                    "mma.sync.aligned.m16n8k16.row.col.f32.f16.f16.f32 "
                    "{%0,%1,%2,%3}, {%4,%5,%6,%7}, {%8,%9}, {%0,%1,%2,%3};"
                    : "+f"(acc[mf][nf][0]), "+f"(acc[mf][nf][1]),
                      "+f"(acc[mf][nf][2]), "+f"(acc[mf][nf][3])
                    : "r"(a[mf][0]), "r"(a[mf][1]), "r"(a[mf][2]), "r"(a[mf][3]),
                      "r"(b[nf][0]), "r"(b[nf][1]));
    }
}

__global__ void __launch_bounds__(256, 1) k3_adj_gemm(const int* __restrict__ adj) {
    extern __shared__ char sm3[];
    uint32_t sb = smem_u32(sm3);
    int tid = threadIdx.x, lane = tid & 31, wid = tid >> 5;
    int wm = wid & 3, wn = wid >> 2;          // 4 (M) x 2 (N) warps
    int lt = lane >> 3, lr = lane & 7;
    int mtile = blockIdx.x >> 1, sp = blockIdx.x & 1;
    int i0 = mtile * MT, jb = sp * KSPLIT;

    // A per-lane base: row = wm*32 + (lane>>2), k-pair col = (lane&3)*2 ints = *8 bytes
    uint32_t aoff = (uint32_t)((wm * 32 + (lane >> 2)) * APITCH + (lane & 3) * 8);
    // B ldmatrix per-lane offsets (pre-swizzle), identical to proven layout
    uint32_t brow4[4], brow2;
#pragma unroll
    for (int g4 = 0; g4 < 4; ++g4)
        brow4[g4] = (uint32_t)((wn * 72 + g4 * 16 + (lt >> 1) * 8 + lr) * 128 + (lt & 1) * 16);
    brow2 = (uint32_t)((wn * 72 + 64 + lr) * 128 + (lt & 1) * 16);

    float acc[2][9][4];
#pragma unroll
    for (int mf = 0; mf < 2; ++mf)
#pragma unroll
        for (int nf = 0; nf < 9; ++nf)
#pragma unroll
            for (int q = 0; q < 4; ++q) acc[mf][nf][q] = 0.f;

    // prologue: stage 0..2 in flight
    stage_load(sb + 0 * STAGEB, adj, i0, jb + 0 * KT, tid);
    stage_load(sb + 1 * STAGEB, adj, i0, jb + 1 * KT, tid);
    stage_load(sb + 2 * STAGEB, adj, i0, jb + 2 * KT, tid);

    for (int it = 0; it < NKI; ++it) {
        if (it < NKI - 2)
            asm volatile("cp.async.wait_group 2;" ::: "memory");
        else
            asm volatile("cp.async.wait_group 0;" ::: "memory");
        __syncthreads();
        if (it + 3 < NKI)
            stage_load(sb + ((it + 3) & 3) * STAGEB, adj, i0, jb + (it + 3) * KT, tid);
        uint32_t Sb = sb + (it & 3) * STAGEB;
        compute_iter(Sb, Sb + ABYTES, acc, aoff, brow4, brow2);
    }

    // epilogue: store split-K partials
    int r0 = i0 + wm * 32 + (lane >> 2);
    int c0 = wn * 72 + (lane & 3) * 2;
    float* base = g_part + (size_t)sp * NN * NCP;
#pragma unroll
    for (int mf = 0; mf < 2; ++mf)
#pragma unroll
        for (int nf = 0; nf < 9; ++nf) {
            int row = r0 + mf * 16, col = c0 + nf * 8;
            *(float2*)(base + (size_t)row * NCP + col) =
                make_float2(acc[mf][nf][0], acc[mf][nf][1]);
            *(float2*)(base + (size_t)(row + 8) * NCP + col) =
                make_float2(acc[mf][nf][2], acc[mf][nf][3]);
        }
}

// ======================= k4: combine splits + divide =======================
__global__ void __launch_bounds__(256) k4_finalize(float* __restrict__ out) {
    int g = blockIdx.x * 256 + threadIdx.x;   // over 8192*128
    int i = g >> 7, c = g & 127;
    const float* p0 = g_part + (size_t)i * NCP;
    const float* p1 = g_part + ((size_t)NN + i) * NCP;
    float num = p0[c] + p1[c];
    int hh = c >> 6;
    float den = p0[128 + hh] + p1[128 + hh];
    out[g] = num / den;
}

// ======================= launch =======================
extern "C" void kernel_launch(void* const* d_in, const int* in_sizes, int n_in,
                              void* d_out, int out_size) {
    (void)in_sizes; (void)n_in; (void)out_size;
    const float* x      = (const float*)d_in[0];
    const int*   adj    = (const int*)d_in[1];
    const float* W      = (const float*)d_in[2];
    // d_in[3] = attn_l : cancels in the softmax over j — unused
    const float* attn_r = (const float*)d_in[4];
    float* out = (float*)d_out;

    cudaFuncSetAttribute(k3_adj_gemm, cudaFuncAttributeMaxDynamicSharedMemorySize, SMEM3);

    k1_h_gemm<<<128, 256>>>(x, W);
    k2a_er<<<32, 256>>>(attn_r);
    k2b_build_g<<<32, 256>>>();
    k3_adj_gemm<<<128, 256, SMEM3>>>(adj);
    k4_finalize<<<4096, 256>>>(out);
}

// round 10
// speedup vs baseline: 1.2585x; 1.0785x over previous
#include <cuda_runtime.h>
#include <cuda_fp16.h>
#include <cstdint>

// Problem constants
#define NN     8192
#define INDIM  256
#define DTOT   128      // OUT_DIM * HEADS
#define NCP    144      // padded GEMM N: 128 outputs + 2 denominators + 14 zero pad
#define MT     128      // M tile
#define KT     64       // K tile
#define NSPLIT 4        // split-K factor
#define KSPLIT 2048     // K per split
#define NKI    32       // K iterations per split

// -------- static device scratch (no allocations allowed) --------
__device__ float     g_h[NN * DTOT];            // 4 MB   h = x @ W^T (fp32)
__device__ float     g_er[2 * NN];              // er per head
__device__ unsigned  g_maxkey[2];               // encoded global max of er per head
__device__ __half    g_g[NCP * NN];             // 2.25 MB  G^T fp16 [NCP][NN]
__device__ float     g_part[(size_t)NSPLIT * NN * NCP];  // 18.9 MB split-K partials

__device__ __forceinline__ uint32_t smem_u32(const void* p) {
    uint32_t a;
    asm("{ .reg .u64 t; cvta.to.shared.u64 t, %1; cvt.u32.u64 %0, t; }" : "=r"(a) : "l"(p));
    return a;
}
#define SWZ(off) ((off) ^ (((off) >> 3) & 0x70))

// ordered-uint encoding for float atomicMax
__device__ __forceinline__ unsigned enc_f(float f) {
    unsigned b = __float_as_uint(f);
    return (b & 0x80000000u) ? ~b : (b | 0x80000000u);
}
__device__ __forceinline__ float dec_f(unsigned k) {
    return (k & 0x80000000u) ? __uint_as_float(k & 0x7FFFFFFFu) : __uint_as_float(~k);
}

// ======================= k1: h = x @ W^T (fp32, register tiled) =======================
__global__ void __launch_bounds__(256) k1_h_gemm(const float* __restrict__ x,
                                                const float* __restrict__ W) {
    if (blockIdx.x == 0 && threadIdx.x < 2) g_maxkey[threadIdx.x] = 0u;  // reset for k2a

    __shared__ __align__(16) float xs[32][132];  // k-major [kk][i]
    __shared__ __align__(16) float ws[32][68];   // k-major [kk][c]
    int tid = threadIdx.x;
    int mtile = blockIdx.x >> 1, ntile = blockIdx.x & 1;
    int i0 = mtile * 128, n0 = ntile * 64;
    int tx = tid & 15, ty = tid >> 4;
    int r0 = ty * 8, c0 = tx * 4;

    float acc[8][4];
#pragma unroll
    for (int m = 0; m < 8; ++m)
#pragma unroll
        for (int n = 0; n < 4; ++n) acc[m][n] = 0.f;

    for (int kc = 0; kc < 8; ++kc) {
        int k0 = kc * 32;
#pragma unroll
        for (int i = 0; i < 4; ++i) {          // x tile: 1024 float4
            int q = tid + i * 256;
            int r = q >> 3, c4 = q & 7;
            float4 v = *(const float4*)(x + (size_t)(i0 + r) * INDIM + k0 + c4 * 4);
            xs[c4 * 4 + 0][r] = v.x; xs[c4 * 4 + 1][r] = v.y;
            xs[c4 * 4 + 2][r] = v.z; xs[c4 * 4 + 3][r] = v.w;
        }
#pragma unroll
        for (int i = 0; i < 2; ++i) {          // W tile: 512 float4
            int q = tid + i * 256;
            int r = q >> 3, c4 = q & 7;
            float4 v = *(const float4*)(W + (size_t)(n0 + r) * INDIM + k0 + c4 * 4);
            ws[c4 * 4 + 0][r] = v.x; ws[c4 * 4 + 1][r] = v.y;
            ws[c4 * 4 + 2][r] = v.z; ws[c4 * 4 + 3][r] = v.w;
        }
        __syncthreads();
#pragma unroll
        for (int kk = 0; kk < 32; ++kk) {
            float4 a0 = *(const float4*)&xs[kk][r0];
            float4 a1 = *(const float4*)&xs[kk][r0 + 4];
            float4 bv = *(const float4*)&ws[kk][c0];
            float a[8] = {a0.x, a0.y, a0.z, a0.w, a1.x, a1.y, a1.z, a1.w};
            float b[4] = {bv.x, bv.y, bv.z, bv.w};
#pragma unroll
            for (int m = 0; m < 8; ++m)
#pragma unroll
                for (int n = 0; n < 4; ++n) acc[m][n] += a[m] * b[n];
        }
        __syncthreads();
    }
#pragma unroll
    for (int m = 0; m < 8; ++m) {
        float4 v = make_float4(acc[m][0], acc[m][1], acc[m][2], acc[m][3]);
        *(float4*)(g_h + (size_t)(i0 + r0 + m) * DTOT + n0 + c0) = v;
    }
}

// ======================= k2a: er[j,h] + global max per head =======================
__global__ void __launch_bounds__(256) k2a_er(const float* __restrict__ attn_r) {
    int tid = threadIdx.x, lane = tid & 31, wid = tid >> 5;
    int j = blockIdx.x * 256 + tid;
    const float* hp = g_h + (size_t)j * DTOT;
    float er0 = 0.f, er1 = 0.f;
#pragma unroll
    for (int d = 0; d < 64; ++d) {
        er0 += hp[d]      * attn_r[d];
        er1 += hp[64 + d] * attn_r[64 + d];
    }
    g_er[j] = er0;
    g_er[NN + j] = er1;

    float m0 = er0, m1 = er1;
#pragma unroll
    for (int o = 16; o; o >>= 1) {
        m0 = fmaxf(m0, __shfl_xor_sync(0xFFFFFFFFu, m0, o));
        m1 = fmaxf(m1, __shfl_xor_sync(0xFFFFFFFFu, m1, o));
    }
    __shared__ float s0[8], s1[8];
    if (lane == 0) { s0[wid] = m0; s1[wid] = m1; }
    __syncthreads();
    if (tid == 0) {
#pragma unroll
        for (int w = 1; w < 8; ++w) { m0 = fmaxf(m0, s0[w]); m1 = fmaxf(m1, s1[w]); }
        m0 = fmaxf(m0, s0[0]); m1 = fmaxf(m1, s1[0]);
        atomicMax(&g_maxkey[0], enc_f(m0));
        atomicMax(&g_maxkey[1], enc_f(m1));
    }
}

// ======================= k2b: G^T = exp(er - max) * h  (fp16) =======================
__global__ void __launch_bounds__(256) k2b_build_g() {
    int j = blockIdx.x * 256 + threadIdx.x;
    float m0 = dec_f(g_maxkey[0]), m1 = dec_f(g_maxkey[1]);
    float E0 = expf(g_er[j] - m0);
    float E1 = expf(g_er[NN + j] - m1);
    const float* hp = g_h + (size_t)j * DTOT;
    float hr[128];
#pragma unroll
    for (int i = 0; i < 32; ++i) {
        float4 v = *(const float4*)(hp + i * 4);
        hr[i * 4 + 0] = v.x; hr[i * 4 + 1] = v.y; hr[i * 4 + 2] = v.z; hr[i * 4 + 3] = v.w;
    }
#pragma unroll
    for (int c = 0; c < 128; ++c) {
        float v = (c < 64 ? E0 : E1) * hr[c];
        g_g[(size_t)c * NN + j] = __float2half(v);
    }
    g_g[(size_t)128 * NN + j] = __float2half(E0);
    g_g[(size_t)129 * NN + j] = __float2half(E1);
#pragma unroll
    for (int c = 130; c < NCP; ++c) g_g[(size_t)c * NN + j] = __float2half(0.f);
}

// ======================= k3: [num|den] = f16(adj) @ G  (mma.sync, 2-stage, 2 CTAs/SM) =======================
// per stage: A as raw int32, 128 rows x 272B pitch (34816 B) ; B fp16 SW128 144x128B (18432 B)
#define APITCH 272
#define ABYTES 34816
#define STAGEB 53248
#define NSTG   2
#define SMEM3  (NSTG * STAGEB)

__device__ __forceinline__ void stage_load(uint32_t Sb, const int* __restrict__ adj,
                                           int i0, int j0, int tid) {
    uint32_t Ab = Sb, Bb = Sb + ABYTES;
    // A: 128 rows x 16 chunks of 16B (raw int32, no conversion)
#pragma unroll
    for (int i = 0; i < 8; ++i) {
        int q = tid + i * 256;
        int r = q >> 4, ch = q & 15;
        uint32_t dst = Ab + (uint32_t)(r * APITCH + ch * 16);
        const void* src = adj + (size_t)(i0 + r) * NN + j0 + ch * 4;
        asm volatile("cp.async.cg.shared.global [%0], [%1], 16;" :: "r"(dst), "l"(src));
    }
    // B: 144 rows x 8 chunks of 16B, SW128
#pragma unroll
    for (int i = 0; i < 5; ++i) {
        int q = tid + i * 256;
        if (q < NCP * 8) {
            int n = q >> 3, c = q & 7;
            uint32_t dst = Bb + SWZ((uint32_t)(n * 128 + c * 16));
            const void* src = (const char*)g_g + ((size_t)n * NN + j0) * 2 + c * 16;
            asm volatile("cp.async.cg.shared.global [%0], [%1], 16;" :: "r"(dst), "l"(src));
        }
    }
    asm volatile("cp.async.commit_group;" ::: "memory");
}

__device__ __forceinline__ void compute_iter(uint32_t Ab, uint32_t Bb,
                                             float acc[2][9][4],
                                             uint32_t aoff,
                                             const uint32_t brow4[4],
                                             uint32_t brow2) {
#pragma unroll
    for (int s = 0; s < 4; ++s) {
        uint32_t kb = s * 32;   // B byte offset within row (16 halfs per k-step)
        uint32_t ka = s * 64;   // A byte offset within row (16 ints per k-step)
        uint32_t a[2][4];
#pragma unroll
        for (int mf = 0; mf < 2; ++mf) {
            uint32_t base = Ab + aoff + (uint32_t)(mf * 16 * APITCH) + ka;
            uint32_t x0, y0, x1, y1, x2, y2, x3, y3;
            asm("ld.shared.v2.u32 {%0,%1}, [%2];" : "=r"(x0), "=r"(y0) : "r"(base));
            asm("ld.shared.v2.u32 {%0,%1}, [%2];" : "=r"(x1), "=r"(y1) : "r"(base + 8 * APITCH));
            asm("ld.shared.v2.u32 {%0,%1}, [%2];" : "=r"(x2), "=r"(y2) : "r"(base + 32));
            asm("ld.shared.v2.u32 {%0,%1}, [%2];" : "=r"(x3), "=r"(y3) : "r"(base + 8 * APITCH + 32));
            a[mf][0] = (x0 | (y0 << 16)) * 0x3C00u;
            a[mf][1] = (x1 | (y1 << 16)) * 0x3C00u;
            a[mf][2] = (x2 | (y2 << 16)) * 0x3C00u;
            a[mf][3] = (x3 | (y3 << 16)) * 0x3C00u;
        }
        uint32_t b[9][2];
#pragma unroll
        for (int g4 = 0; g4 < 4; ++g4) {
            uint32_t bd = Bb + SWZ(brow4[g4] + kb);
            asm volatile("ldmatrix.sync.aligned.m8n8.x4.shared.b16 {%0,%1,%2,%3}, [%4];"
                : "=r"(b[2 * g4][0]), "=r"(b[2 * g4][1]),
                  "=r"(b[2 * g4 + 1][0]), "=r"(b[2 * g4 + 1][1]) : "r"(bd));
        }
        {
            uint32_t bd = Bb + SWZ(brow2 + kb);
            asm volatile("ldmatrix.sync.aligned.m8n8.x2.shared.b16 {%0,%1}, [%2];"
                : "=r"(b[8][0]), "=r"(b[8][1]) : "r"(bd));
        }
#pragma unroll
        for (int mf = 0; mf < 2; ++mf)
#pragma unroll
            for (int nf = 0; nf < 9; ++nf)
                asm volatile(
                    "mma.sync.aligned.m16n8k16.row.col.f32.f16.f16.f32 "
                    "{%0,%1,%2,%3}, {%4,%5,%6,%7}, {%8,%9}, {%0,%1,%2,%3};"
                    : "+f"(acc[mf][nf][0]), "+f"(acc[mf][nf][1]),
                      "+f"(acc[mf][nf][2]), "+f"(acc[mf][nf][3])
                    : "r"(a[mf][0]), "r"(a[mf][1]), "r"(a[mf][2]), "r"(a[mf][3]),
                      "r"(b[nf][0]), "r"(b[nf][1]));
    }
}

__global__ void __launch_bounds__(256, 2) k3_adj_gemm(const int* __restrict__ adj) {
    extern __shared__ char sm3[];
    uint32_t sb = smem_u32(sm3);
    int tid = threadIdx.x, lane = tid & 31, wid = tid >> 5;
    int wm = wid & 3, wn = wid >> 2;          // 4 (M) x 2 (N) warps
    int lt = lane >> 3, lr = lane & 7;
    int mtile = blockIdx.x >> 2, sp = blockIdx.x & 3;
    int i0 = mtile * MT, jb = sp * KSPLIT;

    // A per-lane base: row = wm*32 + (lane>>2), k-pair col = (lane&3)*2 ints = *8 bytes
    uint32_t aoff = (uint32_t)((wm * 32 + (lane >> 2)) * APITCH + (lane & 3) * 8);
    // B ldmatrix per-lane offsets (pre-swizzle)
    uint32_t brow4[4], brow2;
#pragma unroll
    for (int g4 = 0; g4 < 4; ++g4)
        brow4[g4] = (uint32_t)((wn * 72 + g4 * 16 + (lt >> 1) * 8 + lr) * 128 + (lt & 1) * 16);
    brow2 = (uint32_t)((wn * 72 + 64 + lr) * 128 + (lt & 1) * 16);

    float acc[2][9][4];
#pragma unroll
    for (int mf = 0; mf < 2; ++mf)
#pragma unroll
        for (int nf = 0; nf < 9; ++nf)
#pragma unroll
            for (int q = 0; q < 4; ++q) acc[mf][nf][q] = 0.f;

    // prologue: both stages in flight
    stage_load(sb + 0 * STAGEB, adj, i0, jb + 0 * KT, tid);
    stage_load(sb + 1 * STAGEB, adj, i0, jb + 1 * KT, tid);

    for (int it = 0; it < NKI; ++it) {
        if (it < NKI - 1)
            asm volatile("cp.async.wait_group 1;" ::: "memory");
        else
            asm volatile("cp.async.wait_group 0;" ::: "memory");
        __syncthreads();
        uint32_t Sb = sb + (it & 1) * STAGEB;
        compute_iter(Sb, Sb + ABYTES, acc, aoff, brow4, brow2);
        if (it + 2 < NKI) {
            __syncthreads();   // all warps done reading this buffer
            stage_load(Sb, adj, i0, jb + (it + 2) * KT, tid);
        }
    }

    // epilogue: store split-K partials
    int r0 = i0 + wm * 32 + (lane >> 2);
    int c0 = wn * 72 + (lane & 3) * 2;
    float* base = g_part + (size_t)sp * NN * NCP;
#pragma unroll
    for (int mf = 0; mf < 2; ++mf)
#pragma unroll
        for (int nf = 0; nf < 9; ++nf) {
            int row = r0 + mf * 16, col = c0 + nf * 8;
            *(float2*)(base + (size_t)row * NCP + col) =
                make_float2(acc[mf][nf][0], acc[mf][nf][1]);
            *(float2*)(base + (size_t)(row + 8) * NCP + col) =
                make_float2(acc[mf][nf][2], acc[mf][nf][3]);
        }
}

// ======================= k4: combine splits + divide =======================
__global__ void __launch_bounds__(256) k4_finalize(float* __restrict__ out) {
    int g = blockIdx.x * 256 + threadIdx.x;   // over 8192*128
    int i = g >> 7, c = g & 127;
    int hh = c >> 6;
    float num = 0.f, den = 0.f;
#pragma unroll
    for (int s = 0; s < NSPLIT; ++s) {
        const float* p = g_part + ((size_t)s * NN + i) * NCP;
        num += p[c];
        den += p[128 + hh];
    }
    out[g] = num / den;
}

// ======================= launch =======================
extern "C" void kernel_launch(void* const* d_in, const int* in_sizes, int n_in,
                              void* d_out, int out_size) {
    (void)in_sizes; (void)n_in; (void)out_size;
    const float* x      = (const float*)d_in[0];
    const int*   adj    = (const int*)d_in[1];
    const float* W      = (const float*)d_in[2];
    // d_in[3] = attn_l : cancels in the softmax over j — unused
    const float* attn_r = (const float*)d_in[4];
    float* out = (float*)d_out;

    cudaFuncSetAttribute(k3_adj_gemm, cudaFuncAttributeMaxDynamicSharedMemorySize, SMEM3);

    k1_h_gemm<<<128, 256>>>(x, W);
    k2a_er<<<32, 256>>>(attn_r);
    k2b_build_g<<<32, 256>>>();
    k3_adj_gemm<<<256, 256, SMEM3>>>(adj);
    k4_finalize<<<4096, 256>>>(out);
}